// round 8
// baseline (speedup 1.0000x reference)
#include <cuda_runtime.h>
#include <math.h>
#include <stdint.h>

#define H 768
#define R 64
#define E 8
#define T_TOT 16384
#define T_TILE 128

// ---------------- device global scratch -----------------------------------
__device__ int   g_counts[E];
__device__ int   g_toks[E * T_TOT];
__device__ float g_pmax[T_TOT];
__device__ float g_wc[H * E];    // combined router weight, c-interleaved layout
__device__ float g_bc[E];        // combined router bias

// ---------------- helpers ---------------------------------------------------
__device__ __forceinline__ float tf32f(float v) {
    uint32_t r; asm("cvt.rna.tf32.f32 %0, %1;" : "=r"(r) : "f"(v));
    return __uint_as_float(r);
}
__device__ __forceinline__ float gelu(float v) {
    return 0.5f * v * (1.0f + erff(v * 0.70710678118654752f));
}
__device__ __forceinline__ void mma_tf32(float c[4], uint32_t a0, uint32_t a1,
                                         uint32_t a2, uint32_t a3,
                                         uint32_t b0, uint32_t b1) {
    asm volatile(
        "mma.sync.aligned.m16n8k8.row.col.f32.tf32.tf32.f32 "
        "{%0,%1,%2,%3}, {%4,%5,%6,%7}, {%8,%9}, {%0,%1,%2,%3};"
        : "+f"(c[0]), "+f"(c[1]), "+f"(c[2]), "+f"(c[3])
        : "r"(a0), "r"(a1), "r"(a2), "r"(a3), "r"(b0), "r"(b1));
}
#define FB(x) __float_as_uint(x)

// ---------------- router prep: W_comb = enc_w @ sw_w  -----------------------
// Stored c-interleaved: entry (h, e) at [ ((h&3)*192 + (h>>2))*8 + e ].
// sw_w staged in smem; enc_w row read as 16 independent float4 (MLP).
__global__ __launch_bounds__(256) void router_prep_kernel(
    const float* __restrict__ enc_w, const float* __restrict__ enc_b,
    const float* __restrict__ sw_w,  const float* __restrict__ sw_b)
{
    __shared__ float sws[R * E];
    const int tid = threadIdx.x;
    sws[tid]       = sw_w[tid];
    sws[tid + 256] = sw_w[tid + 256];
    __syncthreads();

    const int idx = blockIdx.x * 256 + tid;       // 24 blocks -> 6144 = H*E
    const int h = idx >> 3, e = idx & 7;
    const float4* ew = (const float4*)(enc_w + (size_t)h * R);
    float4 v[16];
#pragma unroll
    for (int i = 0; i < 16; i++) v[i] = ew[i];
    float acc = 0.f;
#pragma unroll
    for (int i = 0; i < 16; i++) {
        acc = fmaf(v[i].x, sws[(i * 4 + 0) * 8 + e], acc);
        acc = fmaf(v[i].y, sws[(i * 4 + 1) * 8 + e], acc);
        acc = fmaf(v[i].z, sws[(i * 4 + 2) * 8 + e], acc);
        acc = fmaf(v[i].w, sws[(i * 4 + 3) * 8 + e], acc);
    }
    g_wc[((h & 3) * 192 + (h >> 2)) * 8 + e] = acc;

    if (blockIdx.x == 0 && tid < E) {
        float s = sw_b[tid];
#pragma unroll
        for (int r = 0; r < R; r++) s = fmaf(enc_b[r], sws[r * E + tid], s);
        g_bc[tid] = s;
        g_counts[tid] = 0;
    }
}

// ---------------- router: logits = x @ W_comb + b_comb (proven) -------------
__global__ __launch_bounds__(256) void router_lite_kernel(const float* __restrict__ x)
{
    const int tid  = threadIdx.x;
    const int wid  = tid >> 5;
    const int lane = tid & 31;
    const int tb   = (blockIdx.x * 8 + wid) * 4;

    float acc[4][8];
#pragma unroll
    for (int t = 0; t < 4; t++)
#pragma unroll
        for (int e = 0; e < 8; e++) acc[t][e] = 0.f;

    const float* xp0 = x + (size_t)tb * H + lane * 4;

#pragma unroll
    for (int j = 0; j < 6; j++) {
        float4 xv[4];
#pragma unroll
        for (int t = 0; t < 4; t++)
            xv[t] = *(const float4*)(xp0 + (size_t)t * H + j * 128);
#pragma unroll
        for (int c = 0; c < 4; c++) {
            const float* wrow = g_wc + ((size_t)(c * 192 + j * 32 + lane) * 8);
            float4 w0 = *(const float4*)wrow;
            float4 w1 = *(const float4*)(wrow + 4);
#pragma unroll
            for (int t = 0; t < 4; t++) {
                float xs = (c == 0) ? xv[t].x : (c == 1) ? xv[t].y
                          : (c == 2) ? xv[t].z : xv[t].w;
                acc[t][0] += xs * w0.x; acc[t][1] += xs * w0.y;
                acc[t][2] += xs * w0.z; acc[t][3] += xs * w0.w;
                acc[t][4] += xs * w1.x; acc[t][5] += xs * w1.y;
                acc[t][6] += xs * w1.z; acc[t][7] += xs * w1.w;
            }
        }
    }

    float a[32];
#pragma unroll
    for (int t = 0; t < 4; t++)
#pragma unroll
        for (int e = 0; e < 8; e++) a[t * 8 + e] = acc[t][e];

#pragma unroll
    for (int r = 0; r < 5; r++) {
        const int hn = 16 >> r;
        const bool up = (lane >> r) & 1;
#pragma unroll
        for (int j2 = 0; j2 < hn; j2++) {
            float pay  = up ? a[2 * j2] : a[2 * j2 + 1];
            float rec  = __shfl_xor_sync(0xffffffffu, pay, 1 << r);
            float keep = up ? a[2 * j2 + 1] : a[2 * j2];
            a[j2] = keep + rec;
        }
    }

    const int e    = lane & 7;
    const int tloc = lane >> 3;
    float l = a[0] + g_bc[e];

    float m = l; int am = e;
#pragma unroll
    for (int off = 4; off >= 1; off >>= 1) {
        float om = __shfl_xor_sync(0xffffffffu, m, off);
        int   oa = __shfl_xor_sync(0xffffffffu, am, off);
        if (om > m || (om == m && oa < am)) { m = om; am = oa; }
    }
    float s = expf(l - m);
#pragma unroll
    for (int off = 4; off >= 1; off >>= 1) s += __shfl_xor_sync(0xffffffffu, s, off);

    if (e == 0) {
        int t = tb + tloc;
        g_pmax[t] = 1.0f / s;
        int slot = atomicAdd(&g_counts[am], 1);
        g_toks[am * T_TOT + slot] = t;
    }
}

// ---------------- expert kernel: fragment-packed smem + mma tf32 ------------
// smem (bytes):
//   POOL @0 (65536): phase1 XS2 [2][4096]f @0 (32KB) + WS1 [2][2048]f @32768 (16KB)
//                    phase2 W2S2 [2][8192]f @0 (64KB)
//   HS2  @65536 (32KB): 2048 float4, fragment-packed gelu(h)
//   TOK @98304, PM @98816, B1S @99328, B2S @99584 (2x128)
#define OFF_POOL  0
#define OFF_WS1   32768
#define OFF_HS    65536
#define OFF_TOK   98304
#define OFF_PM    98816
#define OFF_B1S   99328
#define OFF_B2S   99584
#define SMEM_TOTAL 100608

__global__ void __launch_bounds__(256)
expert_mma_kernel(const float* __restrict__ x,  const float* __restrict__ w1,
                  const float* __restrict__ b1, const float* __restrict__ w2,
                  const float* __restrict__ b2, float* __restrict__ outp)
{
    extern __shared__ char smem[];
    const int e   = blockIdx.y;
    const int cnt = g_counts[e];
    const int t0  = blockIdx.x * T_TILE;
    if (t0 >= cnt) return;
    const int nt_lim = min(T_TILE, cnt - t0);

    const int tid  = threadIdx.x;
    const int wid  = tid >> 5;
    const int lane = tid & 31;
    const int lr   = lane >> 2;
    const int lc   = lane & 3;
    const int m0   = wid * 16;
    const int vb   = lc * 8 + lr;     // B-fragment lane index

    float* Xf   = (float*)(smem + OFF_POOL);
    float* Wf   = (float*)(smem + OFF_WS1);
    float* W2f  = (float*)(smem + OFF_POOL);
    float* HSf  = (float*)(smem + OFF_HS);
    int*   toks = (int*)(smem + OFF_TOK);
    float* pm_s = (float*)(smem + OFF_PM);
    float* b1s  = (float*)(smem + OFF_B1S);
    float* b2s  = (float*)(smem + OFF_B2S);

    if (tid < 128) {
        int idx = t0 + ((tid < nt_lim) ? tid : 0);
        int tok = g_toks[e * T_TOT + idx];
        toks[tid] = tok;
        pm_s[tid] = g_pmax[tok];
    }
    if (tid < 64) b1s[tid] = b1[e * R + tid];
    __syncthreads();

    // ======== Phase 1: C1[128,64] = X[128,768] @ W1[768,64] ========
    const float* w1e = w1 + (size_t)e * H * R;
    const float* xgp[4];
    int xo[4][4];                      // precomputed packed store offsets (x)
#pragma unroll
    for (int j = 0; j < 4; j++) {
        int i = tid + j * 256;
        int row = i >> 3, k4 = (i & 7) << 2;
        xgp[j] = x + (size_t)toks[row] * H + k4;
        int wb = row >> 4, lrs = row & 7, hi = (row >> 3) & 1;
        int ks = k4 >> 3, h4 = (k4 >> 2) & 1;
        int base = ((wb * 4 + ks) * 32 + lrs * 4) * 4 + (hi + 2 * h4);
#pragma unroll
        for (int c = 0; c < 4; c++) xo[j][c] = base + 4 * (c ^ ks);
    }
    const float* wgp[2];
    int wo[2][4];                      // precomputed packed store offsets (w1)
#pragma unroll
    for (int j = 0; j < 2; j++) {
        int i = tid + j * 256;
        int kr = i >> 4, n4 = (i & 15) << 2;
        wgp[j] = w1e + (size_t)kr * R + n4;
        int ks = kr >> 3, lcb = kr & 3, h = (kr >> 2) & 1;
        int nt = n4 >> 3, lr0 = n4 & 7;
#pragma unroll
        for (int c = 0; c < 4; c++)
            wo[j][c] = ((ks * 8 + nt) * 32 + lcb * 8 + ((lr0 + c) ^ nt)) * 2 + h;
    }

    float4 xr[4], wr[2];
#define P1_LOAD(k0) { \
    _Pragma("unroll") for (int j = 0; j < 4; j++) xr[j] = *(const float4*)(xgp[j] + (k0)); \
    _Pragma("unroll") for (int j = 0; j < 2; j++) wr[j] = *(const float4*)(wgp[j] + (size_t)(k0) * R); }
#define P1_STORE(bf) { \
    const int xb_ = (bf) * 4096, wb_ = (bf) * 2048; \
    _Pragma("unroll") for (int j = 0; j < 4; j++) { \
        Xf[xb_ + xo[j][0]] = tf32f(xr[j].x); Xf[xb_ + xo[j][1]] = tf32f(xr[j].y); \
        Xf[xb_ + xo[j][2]] = tf32f(xr[j].z); Xf[xb_ + xo[j][3]] = tf32f(xr[j].w); } \
    _Pragma("unroll") for (int j = 0; j < 2; j++) { \
        Wf[wb_ + wo[j][0]] = tf32f(wr[j].x); Wf[wb_ + wo[j][1]] = tf32f(wr[j].y); \
        Wf[wb_ + wo[j][2]] = tf32f(wr[j].z); Wf[wb_ + wo[j][3]] = tf32f(wr[j].w); } }

    float acc[8][4];
#pragma unroll
    for (int i = 0; i < 8; i++)
#pragma unroll
        for (int j = 0; j < 4; j++) acc[i][j] = 0.f;

    P1_LOAD(0); P1_STORE(0); __syncthreads();
    int p = 0;
    for (int it = 0; it < 24; it++) {
        if (it < 23) P1_LOAD((it + 1) * 32);
        const float4* XA = (const float4*)Xf + (size_t)(p * 32 + wid * 4) * 32;
        const float2* WB = (const float2*)Wf + (size_t)(p * 4) * 256;
#pragma unroll
        for (int ks = 0; ks < 4; ks++) {
            float4 xa = XA[ks * 32 + (lane ^ ks)];
            uint32_t a0 = FB(xa.x), a1 = FB(xa.y), a2 = FB(xa.z), a3 = FB(xa.w);
            const float2* wrow = WB + ks * 256;
#pragma unroll
            for (int nt = 0; nt < 8; nt++) {
                float2 bb = wrow[nt * 32 + (vb ^ nt)];
                mma_tf32(acc[nt], a0, a1, a2, a3, FB(bb.x), FB(bb.y));
            }
        }
        if (it < 23) P1_STORE(p ^ 1);
        __syncthreads();
        p ^= 1;
    }

    // bias + gelu -> HS2 (fragment-packed, tf32-rounded)
    {
        const int lc2 = (2 * lc) & 3;
        const int q2  = 2 * (lc >> 1);
#pragma unroll
        for (int nt1 = 0; nt1 < 8; nt1++) {
            const int cb = nt1 * 8 + 2 * lc;
            const float bva = b1s[cb], bvb = b1s[cb + 1];
            const int base = ((wid * 8 + nt1) * 32 + lr * 4 + lc2) * 4 + q2;
            HSf[base + 0] = tf32f(gelu(acc[nt1][0] + bva));
            HSf[base + 4] = tf32f(gelu(acc[nt1][1] + bvb));
            HSf[base + 1] = tf32f(gelu(acc[nt1][2] + bva));
            HSf[base + 5] = tf32f(gelu(acc[nt1][3] + bvb));
        }
    }
    __syncthreads();

    // ======== Phase 2: out[128,768] = gelu_h[128,64] @ W2[64,768] ========
    const float* w2e = w2 + (size_t)e * R * H;
    const float* w2gp[8];
    int w2o[8][4];
#pragma unroll
    for (int j = 0; j < 8; j++) {
        int i = tid + j * 256;
        int kr = i >> 5, n4 = (i & 31) << 2;
        w2gp[j] = w2e + (size_t)kr * H + n4;
        int ks = kr >> 3, lcb = kr & 3, h = (kr >> 2) & 1;
        int nt = n4 >> 3, lr0 = n4 & 7;
        int lcs = (lcb ^ (nt >> 3)) * 8;
#pragma unroll
        for (int c = 0; c < 4; c++)
            w2o[j][c] = ((ks * 16 + nt) * 32 + lcs + ((lr0 + c) ^ (nt & 7))) * 2 + h;
    }
    float4 w2r[8];
#define P2_LOAD(n0) { \
    _Pragma("unroll") for (int j = 0; j < 8; j++) w2r[j] = *(const float4*)(w2gp[j] + (n0)); }
#define P2_STORE(bf) { \
    const int ob_ = (bf) * 8192; \
    _Pragma("unroll") for (int j = 0; j < 8; j++) { \
        W2f[ob_ + w2o[j][0]] = tf32f(w2r[j].x); W2f[ob_ + w2o[j][1]] = tf32f(w2r[j].y); \
        W2f[ob_ + w2o[j][2]] = tf32f(w2r[j].z); W2f[ob_ + w2o[j][3]] = tf32f(w2r[j].w); } }

    P2_LOAD(0); P2_STORE(0);
    if (tid < 128) b2s[tid] = b2[(size_t)e * H + tid];
    __syncthreads();

    const bool ok0 = (m0 + lr) < nt_lim;
    const bool ok1 = (m0 + lr + 8) < nt_lim;
    const float pm0 = pm_s[m0 + lr];
    const float pm1 = pm_s[m0 + lr + 8];
    float* orow0 = outp + (size_t)toks[m0 + lr] * H;
    float* orow1 = outp + (size_t)toks[m0 + lr + 8] * H;

    // preload phase-2 A fragments (K=64): 8 x LDS.128
    uint32_t af[8][4];
    {
        const float4* HA = (const float4*)HSf + (size_t)(wid * 8) * 32;
#pragma unroll
        for (int ks = 0; ks < 8; ks++) {
            float4 ha = HA[ks * 32 + lane];
            af[ks][0] = FB(ha.x); af[ks][1] = FB(ha.y);
            af[ks][2] = FB(ha.z); af[ks][3] = FB(ha.w);
        }
    }

    int bf = 0;
    for (int nc = 0; nc < 6; nc++) {
        const int n0 = nc * 128;
        if (nc < 5) P2_LOAD(n0 + 128);

        float acc2[16][4];
#pragma unroll
        for (int i = 0; i < 16; i++)
#pragma unroll
            for (int j = 0; j < 4; j++) acc2[i][j] = 0.f;

        const float2* W2B = (const float2*)W2f + (size_t)(bf * 8) * 512;
#pragma unroll
        for (int ks = 0; ks < 8; ks++) {
            const float2* wrow = W2B + ks * 512;
#pragma unroll
            for (int nt = 0; nt < 16; nt++) {
                float2 bb = wrow[nt * 32 + ((lc ^ (nt >> 3)) * 8) + (lr ^ (nt & 7))];
                mma_tf32(acc2[nt], af[ks][0], af[ks][1], af[ks][2], af[ks][3],
                         FB(bb.x), FB(bb.y));
            }
        }

#pragma unroll
        for (int nt = 0; nt < 16; nt++) {
            const int cb = nt * 8 + 2 * lc;
            const float bva = b2s[bf * 128 + cb], bvb = b2s[bf * 128 + cb + 1];
            if (ok0) {
                float2 o = { (acc2[nt][0] + bva) * pm0, (acc2[nt][1] + bvb) * pm0 };
                *(float2*)(orow0 + n0 + cb) = o;
            }
            if (ok1) {
                float2 o = { (acc2[nt][2] + bva) * pm1, (acc2[nt][3] + bvb) * pm1 };
                *(float2*)(orow1 + n0 + cb) = o;
            }
        }

        if (nc < 5) {
            P2_STORE(bf ^ 1);
            if (tid < 128) b2s[(bf ^ 1) * 128 + tid] = b2[(size_t)e * H + n0 + 128 + tid];
        }
        __syncthreads();
        bf ^= 1;
    }
}

// ---------------- launch ----------------------------------------------------
extern "C" void kernel_launch(void* const* d_in, const int* in_sizes, int n_in,
                              void* d_out, int out_size) {
    const float* x     = (const float*)d_in[0];
    const float* enc_w = (const float*)d_in[1];
    const float* enc_b = (const float*)d_in[2];
    const float* sw_w  = (const float*)d_in[3];
    const float* sw_b  = (const float*)d_in[4];
    const float* w1    = (const float*)d_in[5];
    const float* b1    = (const float*)d_in[6];
    const float* w2    = (const float*)d_in[7];
    const float* b2    = (const float*)d_in[8];
    float* out = (float*)d_out;

    cudaFuncSetAttribute(expert_mma_kernel,
                         cudaFuncAttributeMaxDynamicSharedMemorySize, SMEM_TOTAL);

    router_prep_kernel<<<24, 256>>>(enc_w, enc_b, sw_w, sw_b);
    router_lite_kernel<<<T_TOT / 32, 256>>>(x);
    expert_mma_kernel<<<dim3(T_TOT / T_TILE, E), 256, SMEM_TOTAL>>>(
        x, w1, b1, w2, b2, out);
}

// round 12
// speedup vs baseline: 1.1466x; 1.1466x over previous
#include <cuda_runtime.h>
#include <math.h>
#include <stdint.h>

#define H 768
#define R 64
#define E 8
#define T_TOT 16384
#define T_TILE 128

// ---------------- device global scratch -----------------------------------
__device__ int   g_counts[E];
__device__ int   g_toks[E * T_TOT];
__device__ float g_pmax[T_TOT];
__device__ float g_wc[H * E];        // combined router weight (c-interleaved)
__device__ float g_bc[E];            // combined router bias
__device__ float g_w1r[E * H * R];   // tf32-rounded w1
__device__ float g_w2r[E * R * H];   // tf32-rounded w2

// ---------------- helpers ---------------------------------------------------
__device__ __forceinline__ float tf32f(float v) {
    uint32_t r; asm("cvt.rna.tf32.f32 %0, %1;" : "=r"(r) : "f"(v));
    return __uint_as_float(r);
}
__device__ __forceinline__ float gelu(float v) {
    return 0.5f * v * (1.0f + erff(v * 0.70710678118654752f));
}
__device__ __forceinline__ void mma_tf32(float c[4], uint32_t a0, uint32_t a1,
                                         uint32_t a2, uint32_t a3,
                                         uint32_t b0, uint32_t b1) {
    asm volatile(
        "mma.sync.aligned.m16n8k8.row.col.f32.tf32.tf32.f32 "
        "{%0,%1,%2,%3}, {%4,%5,%6,%7}, {%8,%9}, {%0,%1,%2,%3};"
        : "+f"(c[0]), "+f"(c[1]), "+f"(c[2]), "+f"(c[3])
        : "r"(a0), "r"(a1), "r"(a2), "r"(a3), "r"(b0), "r"(b1));
}
#define FB(x) __float_as_uint(x)

__device__ __forceinline__ uint32_t smem_u32(const void* p) {
    uint32_t a;
    asm("{ .reg .u64 t; cvta.to.shared.u64 t, %1; cvt.u32.u64 %0, t; }" : "=r"(a) : "l"(p));
    return a;
}
#define CP16(dst, src) \
    asm volatile("cp.async.cg.shared.global [%0], [%1], 16;" :: "r"(dst), "l"(src))
#define CP_COMMIT() asm volatile("cp.async.commit_group;" ::: "memory")
#define CP_WAIT0()  asm volatile("cp.async.wait_group 0;" ::: "memory")
#define CP_WAIT1()  asm volatile("cp.async.wait_group 1;" ::: "memory")

// ---------------- prep: W_comb + tf32-rounded weight copies -----------------
// blocks 0..23: g_wc/g_bc/counts ; blocks 24..47: round w1 ; 48..71: round w2
__global__ __launch_bounds__(256) void router_prep_kernel(
    const float* __restrict__ enc_w, const float* __restrict__ enc_b,
    const float* __restrict__ sw_w,  const float* __restrict__ sw_b,
    const float* __restrict__ w1,    const float* __restrict__ w2)
{
    const int bid = blockIdx.x, tid = threadIdx.x;
    if (bid < 24) {
        __shared__ float sws[R * E];
        sws[tid]       = sw_w[tid];
        sws[tid + 256] = sw_w[tid + 256];
        __syncthreads();

        const int idx = bid * 256 + tid;
        const int h = idx >> 3, e = idx & 7;
        const float4* ew = (const float4*)(enc_w + (size_t)h * R);
        float4 v[16];
#pragma unroll
        for (int i = 0; i < 16; i++) v[i] = ew[i];
        float acc = 0.f;
#pragma unroll
        for (int i = 0; i < 16; i++) {
            acc = fmaf(v[i].x, sws[(i * 4 + 0) * 8 + e], acc);
            acc = fmaf(v[i].y, sws[(i * 4 + 1) * 8 + e], acc);
            acc = fmaf(v[i].z, sws[(i * 4 + 2) * 8 + e], acc);
            acc = fmaf(v[i].w, sws[(i * 4 + 3) * 8 + e], acc);
        }
        g_wc[((h & 3) * 192 + (h >> 2)) * 8 + e] = acc;

        if (bid == 0 && tid < E) {
            float s = sw_b[tid];
#pragma unroll
            for (int r = 0; r < R; r++) s = fmaf(enc_b[r], sws[r * E + tid], s);
            g_bc[tid] = s;
            g_counts[tid] = 0;
        }
    } else if (bid < 48) {
        const float4* src = (const float4*)w1;
        float4* dst = (float4*)g_w1r;
#pragma unroll
        for (int i = 0; i < 16; i++) {
            int idx = (bid - 24) * 4096 + i * 256 + tid;
            float4 v = src[idx];
            v.x = tf32f(v.x); v.y = tf32f(v.y); v.z = tf32f(v.z); v.w = tf32f(v.w);
            dst[idx] = v;
        }
    } else {
        const float4* src = (const float4*)w2;
        float4* dst = (float4*)g_w2r;
#pragma unroll
        for (int i = 0; i < 16; i++) {
            int idx = (bid - 48) * 4096 + i * 256 + tid;
            float4 v = src[idx];
            v.x = tf32f(v.x); v.y = tf32f(v.y); v.z = tf32f(v.z); v.w = tf32f(v.w);
            dst[idx] = v;
        }
    }
}

// ---------------- router: logits = x @ W_comb + b_comb (proven) -------------
__global__ __launch_bounds__(256) void router_lite_kernel(const float* __restrict__ x)
{
    const int tid  = threadIdx.x;
    const int wid  = tid >> 5;
    const int lane = tid & 31;
    const int tb   = (blockIdx.x * 8 + wid) * 4;

    float acc[4][8];
#pragma unroll
    for (int t = 0; t < 4; t++)
#pragma unroll
        for (int e = 0; e < 8; e++) acc[t][e] = 0.f;

    const float* xp0 = x + (size_t)tb * H + lane * 4;

#pragma unroll
    for (int j = 0; j < 6; j++) {
        float4 xv[4];
#pragma unroll
        for (int t = 0; t < 4; t++)
            xv[t] = *(const float4*)(xp0 + (size_t)t * H + j * 128);
#pragma unroll
        for (int c = 0; c < 4; c++) {
            const float* wrow = g_wc + ((size_t)(c * 192 + j * 32 + lane) * 8);
            float4 w0 = *(const float4*)wrow;
            float4 w1 = *(const float4*)(wrow + 4);
#pragma unroll
            for (int t = 0; t < 4; t++) {
                float xs = (c == 0) ? xv[t].x : (c == 1) ? xv[t].y
                          : (c == 2) ? xv[t].z : xv[t].w;
                acc[t][0] += xs * w0.x; acc[t][1] += xs * w0.y;
                acc[t][2] += xs * w0.z; acc[t][3] += xs * w0.w;
                acc[t][4] += xs * w1.x; acc[t][5] += xs * w1.y;
                acc[t][6] += xs * w1.z; acc[t][7] += xs * w1.w;
            }
        }
    }

    float a[32];
#pragma unroll
    for (int t = 0; t < 4; t++)
#pragma unroll
        for (int e = 0; e < 8; e++) a[t * 8 + e] = acc[t][e];

#pragma unroll
    for (int r = 0; r < 5; r++) {
        const int hn = 16 >> r;
        const bool up = (lane >> r) & 1;
#pragma unroll
        for (int j2 = 0; j2 < hn; j2++) {
            float pay  = up ? a[2 * j2] : a[2 * j2 + 1];
            float rec  = __shfl_xor_sync(0xffffffffu, pay, 1 << r);
            float keep = up ? a[2 * j2 + 1] : a[2 * j2];
            a[j2] = keep + rec;
        }
    }

    const int e    = lane & 7;
    const int tloc = lane >> 3;
    float l = a[0] + g_bc[e];

    float m = l; int am = e;
#pragma unroll
    for (int off = 4; off >= 1; off >>= 1) {
        float om = __shfl_xor_sync(0xffffffffu, m, off);
        int   oa = __shfl_xor_sync(0xffffffffu, am, off);
        if (om > m || (om == m && oa < am)) { m = om; am = oa; }
    }
    float s = expf(l - m);
#pragma unroll
    for (int off = 4; off >= 1; off >>= 1) s += __shfl_xor_sync(0xffffffffu, s, off);

    if (e == 0) {
        int t = tb + tloc;
        g_pmax[t] = 1.0f / s;
        int slot = atomicAdd(&g_counts[am], 1);
        g_toks[am * T_TOT + slot] = t;
    }
}

// ---------------- expert kernel: cp.async pipelines + mma tf32 --------------
// smem (bytes):
//   POOL @0 (82944): phase1 XS[3][128][36] (55296) + WS[3][32][72] @55296 (27648)
//                    phase2 W2S[2][64][136] (69632) overlays
//   HS @82944 (34816); TOK @117760; PM @118272; B1S @118784; B2S @119040
#define XS_B(s)   ((s) * 18432)
#define WS_B(s)   (55296 + (s) * 9216)
#define W2_B(b)   ((b) * 34816)
#define OFF_HS    82944
#define OFF_TOK   117760
#define OFF_PM    118272
#define OFF_B1S   118784
#define OFF_B2S   119040
#define SMEM_TOTAL 120320

#define XS_STR  36
#define WS_STR  72
#define HS_STR  68
#define W2_STR  136

__global__ void __launch_bounds__(256)
expert_mma_kernel(const float* __restrict__ x,
                  const float* __restrict__ b1,
                  const float* __restrict__ b2, float* __restrict__ outp)
{
    extern __shared__ char smem[];
    const int e   = blockIdx.y;
    const int cnt = g_counts[e];
    const int t0  = blockIdx.x * T_TILE;
    if (t0 >= cnt) return;
    const int nt_lim = min(T_TILE, cnt - t0);

    const int tid  = threadIdx.x;
    const int wid  = tid >> 5;
    const int lane = tid & 31;
    const int lr   = lane >> 2;
    const int lc   = lane & 3;
    const int m0   = wid * 16;

    const uint32_t sb = smem_u32(smem);
    float* SM   = (float*)smem;
    float* HSf  = (float*)(smem + OFF_HS);
    int*   toks = (int*)(smem + OFF_TOK);
    float* pm_s = (float*)(smem + OFF_PM);
    float* b1s  = (float*)(smem + OFF_B1S);
    float* b2s  = (float*)(smem + OFF_B2S);

    if (tid < 128) {
        int idx = t0 + ((tid < nt_lim) ? tid : 0);
        int tok = g_toks[e * T_TOT + idx];
        toks[tid] = tok;
        pm_s[tid] = g_pmax[tok];
    }
    if (tid < 64) b1s[tid] = b1[e * R + tid];
    __syncthreads();

    // ======== Phase 1: C1[128,64] = X[128,768] @ W1[768,64] (3-stage) ========
    const float* w1e = g_w1r + (size_t)e * H * R;
    const float* xgp[4]; uint32_t xdst[4];
#pragma unroll
    for (int j = 0; j < 4; j++) {
        int i = tid + j * 256;
        int row = i >> 3, k4 = (i & 7) << 2;
        xgp[j]  = x + (size_t)toks[row] * H + k4;
        xdst[j] = sb + (uint32_t)(row * XS_STR + k4) * 4;
    }
    const float* wgp[2]; uint32_t wdst[2];
#pragma unroll
    for (int j = 0; j < 2; j++) {
        int i = tid + j * 256;
        int kr = i >> 4, n4 = (i & 15) << 2;
        wgp[j]  = w1e + (size_t)kr * R + n4;
        wdst[j] = sb + WS_B(0) + (uint32_t)(kr * WS_STR + n4) * 4;
    }

#define P1_ISSUE(s, k0) { \
    _Pragma("unroll") for (int j = 0; j < 4; j++) \
        CP16(xdst[j] + (s) * 18432, xgp[j] + (k0)); \
    _Pragma("unroll") for (int j = 0; j < 2; j++) \
        CP16(wdst[j] + (s) * 9216, wgp[j] + (size_t)(k0) * R); \
    CP_COMMIT(); }

    float acc[8][4];
#pragma unroll
    for (int i = 0; i < 8; i++)
#pragma unroll
        for (int j = 0; j < 4; j++) acc[i][j] = 0.f;

    P1_ISSUE(0, 0);
    P1_ISSUE(1, 32);

    int s = 0;
    for (int it = 0; it < 24; it++) {
        if (it < 23) { CP_WAIT1(); } else { CP_WAIT0(); }
        __syncthreads();
        if (it < 22) {
            int sn = (s + 2) % 3;
            P1_ISSUE(sn, (it + 2) * 32);
        }
        const float* XA = SM + (size_t)s * 4608 + m0 * XS_STR;
        const float* WB = SM + (WS_B(s) >> 2);
#pragma unroll
        for (int ks = 0; ks < 4; ks++) {
            const int kk = ks * 8;
            const float* xb = XA + kk;
            uint32_t a0 = FB(tf32f(xb[(size_t)lr * XS_STR + lc]));
            uint32_t a1 = FB(tf32f(xb[(size_t)(lr + 8) * XS_STR + lc]));
            uint32_t a2 = FB(tf32f(xb[(size_t)lr * XS_STR + lc + 4]));
            uint32_t a3 = FB(tf32f(xb[(size_t)(lr + 8) * XS_STR + lc + 4]));
            const float* wb0 = WB + (size_t)(kk + lc) * WS_STR + lr;
            const float* wb1 = WB + (size_t)(kk + lc + 4) * WS_STR + lr;
#pragma unroll
            for (int nt = 0; nt < 8; nt++) {
                uint32_t b0 = FB(wb0[nt * 8]);
                uint32_t b1v = FB(wb1[nt * 8]);
                mma_tf32(acc[nt], a0, a1, a2, a3, b0, b1v);
            }
        }
        s = (s + 1) % 3;
    }
    __syncthreads();   // all phase-1 MMAs done before pool reuse

    // bias + gelu -> HS (tf32-rounded)
#pragma unroll
    for (int nt = 0; nt < 8; nt++) {
        const int cb = nt * 8 + 2 * lc;
        const float bva = b1s[cb], bvb = b1s[cb + 1];
        float* h0 = HSf + (size_t)(m0 + lr) * HS_STR + cb;
        float* h1 = HSf + (size_t)(m0 + lr + 8) * HS_STR + cb;
        h0[0] = tf32f(gelu(acc[nt][0] + bva));
        h0[1] = tf32f(gelu(acc[nt][1] + bvb));
        h1[0] = tf32f(gelu(acc[nt][2] + bva));
        h1[1] = tf32f(gelu(acc[nt][3] + bvb));
    }
    __syncthreads();

    // ======== Phase 2: out[128,768] = gelu_h[128,64] @ W2[64,768] ========
    const float* w2e = g_w2r + (size_t)e * R * H;
    const float* w2gp[8]; uint32_t w2dst[8];
#pragma unroll
    for (int j = 0; j < 8; j++) {
        int i = tid + j * 256;
        int kr = i >> 5, n4 = (i & 31) << 2;
        w2gp[j]  = w2e + (size_t)kr * H + n4;
        w2dst[j] = sb + (uint32_t)(kr * W2_STR + n4) * 4;
    }
#define P2_ISSUE(b, n0) { \
    _Pragma("unroll") for (int j = 0; j < 8; j++) \
        CP16(w2dst[j] + (b) * 34816, w2gp[j] + (n0)); \
    CP_COMMIT(); }

    const bool ok0 = (m0 + lr) < nt_lim;
    const bool ok1 = (m0 + lr + 8) < nt_lim;
    const float pm0 = pm_s[m0 + lr];
    const float pm1 = pm_s[m0 + lr + 8];
    float* orow0 = outp + (size_t)toks[m0 + lr] * H;
    float* orow1 = outp + (size_t)toks[m0 + lr + 8] * H;

    // preload phase-2 A fragments (K=64)
    uint32_t af[8][4];
#pragma unroll
    for (int ks = 0; ks < 8; ks++) {
        const int kk = ks * 8;
        const float* hb = HSf + (size_t)m0 * HS_STR + kk;
        af[ks][0] = FB(hb[(size_t)lr * HS_STR + lc]);
        af[ks][1] = FB(hb[(size_t)(lr + 8) * HS_STR + lc]);
        af[ks][2] = FB(hb[(size_t)lr * HS_STR + lc + 4]);
        af[ks][3] = FB(hb[(size_t)(lr + 8) * HS_STR + lc + 4]);
    }

    P2_ISSUE(0, 0);
    if (tid < 128) b2s[tid] = b2[(size_t)e * H + tid];

    int bf = 0;
    for (int nc = 0; nc < 6; nc++) {
        const int n0 = nc * 128;
        CP_WAIT0();
        __syncthreads();
        if (nc < 5) {
            P2_ISSUE(bf ^ 1, n0 + 128);
            if (tid < 128) b2s[(bf ^ 1) * 128 + tid] = b2[(size_t)e * H + n0 + 128 + tid];
        }

        float acc2[16][4];
#pragma unroll
        for (int i = 0; i < 16; i++)
#pragma unroll
            for (int j = 0; j < 4; j++) acc2[i][j] = 0.f;

        const float* W2B = SM + (W2_B(bf) >> 2);
#pragma unroll
        for (int ks = 0; ks < 8; ks++) {
            const int kk = ks * 8;
            const float* wb0 = W2B + (size_t)(kk + lc) * W2_STR + lr;
            const float* wb1 = W2B + (size_t)(kk + lc + 4) * W2_STR + lr;
#pragma unroll
            for (int nt = 0; nt < 16; nt++) {
                uint32_t b0 = FB(wb0[nt * 8]);
                uint32_t b1v = FB(wb1[nt * 8]);
                mma_tf32(acc2[nt], af[ks][0], af[ks][1], af[ks][2], af[ks][3], b0, b1v);
            }
        }

#pragma unroll
        for (int nt = 0; nt < 16; nt++) {
            const int cb = nt * 8 + 2 * lc;
            const float bva = b2s[bf * 128 + cb], bvb = b2s[bf * 128 + cb + 1];
            if (ok0) {
                float2 o = { (acc2[nt][0] + bva) * pm0, (acc2[nt][1] + bvb) * pm0 };
                *(float2*)(orow0 + n0 + cb) = o;
            }
            if (ok1) {
                float2 o = { (acc2[nt][2] + bva) * pm1, (acc2[nt][3] + bvb) * pm1 };
                *(float2*)(orow1 + n0 + cb) = o;
            }
        }
        bf ^= 1;
    }
}

// ---------------- launch ----------------------------------------------------
extern "C" void kernel_launch(void* const* d_in, const int* in_sizes, int n_in,
                              void* d_out, int out_size) {
    const float* x     = (const float*)d_in[0];
    const float* enc_w = (const float*)d_in[1];
    const float* enc_b = (const float*)d_in[2];
    const float* sw_w  = (const float*)d_in[3];
    const float* sw_b  = (const float*)d_in[4];
    const float* w1    = (const float*)d_in[5];
    const float* b1    = (const float*)d_in[6];
    const float* w2    = (const float*)d_in[7];
    const float* b2    = (const float*)d_in[8];
    float* out = (float*)d_out;

    cudaFuncSetAttribute(expert_mma_kernel,
                         cudaFuncAttributeMaxDynamicSharedMemorySize, SMEM_TOTAL);

    router_prep_kernel<<<72, 256>>>(enc_w, enc_b, sw_w, sw_b, w1, w2);
    router_lite_kernel<<<T_TOT / 32, 256>>>(x);
    expert_mma_kernel<<<dim3(T_TOT / T_TILE, E), 256, SMEM_TOTAL>>>(x, b1, b2, out);
}

// round 13
// speedup vs baseline: 1.3013x; 1.1349x over previous
#include <cuda_runtime.h>
#include <math.h>
#include <stdint.h>

#define H 768
#define R 64
#define E 8
#define T_TOT 16384
#define T_TILE 128

// ---------------- device global scratch -----------------------------------
__device__ int   g_counts[E];
__device__ int   g_toks[E * T_TOT];
__device__ float g_pmax[T_TOT];
__device__ float g_wc[H * E];        // combined router weight (c-interleaved)
__device__ float g_bc[E];            // combined router bias
__device__ float g_w1r[E * H * R];   // tf32-rounded w1
__device__ float g_w2r[E * R * H];   // tf32-rounded w2

// ---------------- helpers ---------------------------------------------------
__device__ __forceinline__ float tf32f(float v) {
    uint32_t r; asm("cvt.rna.tf32.f32 %0, %1;" : "=r"(r) : "f"(v));
    return __uint_as_float(r);
}
__device__ __forceinline__ float gelu(float v) {
    return 0.5f * v * (1.0f + erff(v * 0.70710678118654752f));
}
__device__ __forceinline__ void mma_tf32(float c[4], uint32_t a0, uint32_t a1,
                                         uint32_t a2, uint32_t a3,
                                         uint32_t b0, uint32_t b1) {
    asm volatile(
        "mma.sync.aligned.m16n8k8.row.col.f32.tf32.tf32.f32 "
        "{%0,%1,%2,%3}, {%4,%5,%6,%7}, {%8,%9}, {%0,%1,%2,%3};"
        : "+f"(c[0]), "+f"(c[1]), "+f"(c[2]), "+f"(c[3])
        : "r"(a0), "r"(a1), "r"(a2), "r"(a3), "r"(b0), "r"(b1));
}
#define FB(x) __float_as_uint(x)

__device__ __forceinline__ uint32_t smem_u32(const void* p) {
    uint32_t a;
    asm("{ .reg .u64 t; cvta.to.shared.u64 t, %1; cvt.u32.u64 %0, t; }" : "=r"(a) : "l"(p));
    return a;
}
#define CP16(dst, src) \
    asm volatile("cp.async.cg.shared.global [%0], [%1], 16;" :: "r"(dst), "l"(src))
#define CP_COMMIT() asm volatile("cp.async.commit_group;" ::: "memory")
#define CP_WAIT0()  asm volatile("cp.async.wait_group 0;" ::: "memory")
#define CP_WAIT1()  asm volatile("cp.async.wait_group 1;" ::: "memory")

// ---------------- prep: W_comb + tf32-rounded weight copies -----------------
// blocks 0..23: g_wc/g_bc/counts ; 24..71: round w1 ; 72..119: round w2
__global__ __launch_bounds__(256) void router_prep_kernel(
    const float* __restrict__ enc_w, const float* __restrict__ enc_b,
    const float* __restrict__ sw_w,  const float* __restrict__ sw_b,
    const float* __restrict__ w1,    const float* __restrict__ w2)
{
    const int bid = blockIdx.x, tid = threadIdx.x;
    if (bid < 24) {
        __shared__ float sws[R * E];
        sws[tid]       = sw_w[tid];
        sws[tid + 256] = sw_w[tid + 256];
        __syncthreads();

        const int idx = bid * 256 + tid;
        const int h = idx >> 3, e = idx & 7;
        const float4* ew = (const float4*)(enc_w + (size_t)h * R);
        float4 v[16];
#pragma unroll
        for (int i = 0; i < 16; i++) v[i] = ew[i];
        float acc = 0.f;
#pragma unroll
        for (int i = 0; i < 16; i++) {
            acc = fmaf(v[i].x, sws[(i * 4 + 0) * 8 + e], acc);
            acc = fmaf(v[i].y, sws[(i * 4 + 1) * 8 + e], acc);
            acc = fmaf(v[i].z, sws[(i * 4 + 2) * 8 + e], acc);
            acc = fmaf(v[i].w, sws[(i * 4 + 3) * 8 + e], acc);
        }
        g_wc[((h & 3) * 192 + (h >> 2)) * 8 + e] = acc;

        if (bid == 0 && tid < E) {
            float s = sw_b[tid];
#pragma unroll
            for (int r = 0; r < R; r++) s = fmaf(enc_b[r], sws[r * E + tid], s);
            g_bc[tid] = s;
            g_counts[tid] = 0;
        }
    } else if (bid < 72) {
        const float4* src = (const float4*)w1;
        float4* dst = (float4*)g_w1r;
#pragma unroll
        for (int i = 0; i < 8; i++) {
            int idx = (bid - 24) * 2048 + i * 256 + tid;
            float4 v = src[idx];
            v.x = tf32f(v.x); v.y = tf32f(v.y); v.z = tf32f(v.z); v.w = tf32f(v.w);
            dst[idx] = v;
        }
    } else {
        const float4* src = (const float4*)w2;
        float4* dst = (float4*)g_w2r;
#pragma unroll
        for (int i = 0; i < 8; i++) {
            int idx = (bid - 72) * 2048 + i * 256 + tid;
            float4 v = src[idx];
            v.x = tf32f(v.x); v.y = tf32f(v.y); v.z = tf32f(v.z); v.w = tf32f(v.w);
            dst[idx] = v;
        }
    }
}

// ---------------- router: logits = x @ W_comb + b_comb ----------------------
// Block-aggregated bucketing: smem slots + 8 global atomics per block.
__global__ __launch_bounds__(256) void router_lite_kernel(const float* __restrict__ x)
{
    __shared__ int s_cnt[8], s_base[8], s_am[32], s_slot[32];

    const int tid  = threadIdx.x;
    const int wid  = tid >> 5;
    const int lane = tid & 31;
    const int tb   = (blockIdx.x * 8 + wid) * 4;

    if (tid < 8) s_cnt[tid] = 0;

    float acc[4][8];
#pragma unroll
    for (int t = 0; t < 4; t++)
#pragma unroll
        for (int e = 0; e < 8; e++) acc[t][e] = 0.f;

    const float* xp0 = x + (size_t)tb * H + lane * 4;

#pragma unroll
    for (int j = 0; j < 6; j++) {
        float4 xv[4];
#pragma unroll
        for (int t = 0; t < 4; t++)
            xv[t] = *(const float4*)(xp0 + (size_t)t * H + j * 128);
#pragma unroll
        for (int c = 0; c < 4; c++) {
            const float* wrow = g_wc + ((size_t)(c * 192 + j * 32 + lane) * 8);
            float4 w0 = *(const float4*)wrow;
            float4 w1 = *(const float4*)(wrow + 4);
#pragma unroll
            for (int t = 0; t < 4; t++) {
                float xs = (c == 0) ? xv[t].x : (c == 1) ? xv[t].y
                          : (c == 2) ? xv[t].z : xv[t].w;
                acc[t][0] += xs * w0.x; acc[t][1] += xs * w0.y;
                acc[t][2] += xs * w0.z; acc[t][3] += xs * w0.w;
                acc[t][4] += xs * w1.x; acc[t][5] += xs * w1.y;
                acc[t][6] += xs * w1.z; acc[t][7] += xs * w1.w;
            }
        }
    }

    float a[32];
#pragma unroll
    for (int t = 0; t < 4; t++)
#pragma unroll
        for (int e = 0; e < 8; e++) a[t * 8 + e] = acc[t][e];

#pragma unroll
    for (int r = 0; r < 5; r++) {
        const int hn = 16 >> r;
        const bool up = (lane >> r) & 1;
#pragma unroll
        for (int j2 = 0; j2 < hn; j2++) {
            float pay  = up ? a[2 * j2] : a[2 * j2 + 1];
            float rec  = __shfl_xor_sync(0xffffffffu, pay, 1 << r);
            float keep = up ? a[2 * j2 + 1] : a[2 * j2];
            a[j2] = keep + rec;
        }
    }

    const int e    = lane & 7;
    const int tloc = lane >> 3;
    float l = a[0] + g_bc[e];

    float m = l; int am = e;
#pragma unroll
    for (int off = 4; off >= 1; off >>= 1) {
        float om = __shfl_xor_sync(0xffffffffu, m, off);
        int   oa = __shfl_xor_sync(0xffffffffu, am, off);
        if (om > m || (om == m && oa < am)) { m = om; am = oa; }
    }
    float s = expf(l - m);
#pragma unroll
    for (int off = 4; off >= 1; off >>= 1) s += __shfl_xor_sync(0xffffffffu, s, off);

    if (e == 0) {
        int tl = wid * 4 + tloc;
        s_am[tl] = am;
        g_pmax[tb + tloc] = 1.0f / s;
    }
    __syncthreads();                       // orders s_cnt init + s_am writes

    if (tid < 32) {
        s_slot[tid] = atomicAdd(&s_cnt[s_am[tid]], 1);
    }
    __syncthreads();

    if (tid < 8 && s_cnt[tid] > 0)
        s_base[tid] = atomicAdd(&g_counts[tid], s_cnt[tid]);
    __syncthreads();

    if (tid < 32) {
        int am2 = s_am[tid];
        g_toks[am2 * T_TOT + s_base[am2] + s_slot[tid]] = blockIdx.x * 32 + tid;
    }
}

// ---------------- expert kernel: flat grid, 2 blocks/SM, cp.async -----------
// smem (bytes), total 91904 -> 2 blocks/SM:
//   pool @0: phase1 XS[2][128][36] (36864) + WS[2][32][72] @36864 (18432)
//            phase2 W2S[2][64][72] (36864) overlays
//   HS @55296 (34816); TOK @90112; PM @90624; B1S @91136; B2S @91392
#define XS_B(s)   ((s) * 18432)
#define WS_B(s)   (36864 + (s) * 9216)
#define W2_B(b)   ((b) * 18432)
#define OFF_HS    55296
#define OFF_TOK   90112
#define OFF_PM    90624
#define OFF_B1S   91136
#define OFF_B2S   91392
#define SMEM_TOTAL 91904

#define XS_STR  36
#define WS_STR  72
#define HS_STR  68

#define EXPERT_BLOCKS 136   // sum ceil(cnt/128) <= 16384/128 + 7 = 135

__global__ void __launch_bounds__(256, 2)
expert_mma_kernel(const float* __restrict__ x,
                  const float* __restrict__ b1,
                  const float* __restrict__ b2, float* __restrict__ outp)
{
    extern __shared__ char smem[];

    // flat tile lookup: blockIdx.x -> (expert, token-chunk)
    int e = -1, t0 = 0, cnt = 0, accb = 0;
#pragma unroll
    for (int i = 0; i < 8; i++) {
        int c  = g_counts[i];
        int tl = (c + 127) >> 7;
        if (e < 0 && (int)blockIdx.x < accb + tl) {
            e = i; t0 = ((int)blockIdx.x - accb) << 7; cnt = c;
        }
        accb += tl;
    }
    if (e < 0) return;
    const int nt_lim = min(T_TILE, cnt - t0);

    const int tid  = threadIdx.x;
    const int wid  = tid >> 5;
    const int lane = tid & 31;
    const int lr   = lane >> 2;
    const int lc   = lane & 3;
    const int m0   = wid * 16;

    const uint32_t sb = smem_u32(smem);
    float* SM   = (float*)smem;
    float* HSf  = (float*)(smem + OFF_HS);
    int*   toks = (int*)(smem + OFF_TOK);
    float* pm_s = (float*)(smem + OFF_PM);
    float* b1s  = (float*)(smem + OFF_B1S);
    float* b2s  = (float*)(smem + OFF_B2S);

    if (tid < 128) {
        int idx = t0 + ((tid < nt_lim) ? tid : 0);
        int tok = g_toks[e * T_TOT + idx];
        toks[tid] = tok;
        pm_s[tid] = g_pmax[tok];
    }
    if (tid < 64) b1s[tid] = b1[e * R + tid];
    __syncthreads();

    // ======== Phase 1: C1[128,64] = X[128,768] @ W1[768,64] (2-stage) ========
    const float* w1e = g_w1r + (size_t)e * H * R;
    const float* xgp[4]; uint32_t xdst[4];
#pragma unroll
    for (int j = 0; j < 4; j++) {
        int i = tid + j * 256;
        int row = i >> 3, k4 = (i & 7) << 2;
        xgp[j]  = x + (size_t)toks[row] * H + k4;
        xdst[j] = sb + (uint32_t)(row * XS_STR + k4) * 4;
    }
    const float* wgp[2]; uint32_t wdst[2];
#pragma unroll
    for (int j = 0; j < 2; j++) {
        int i = tid + j * 256;
        int kr = i >> 4, n4 = (i & 15) << 2;
        wgp[j]  = w1e + (size_t)kr * R + n4;
        wdst[j] = sb + WS_B(0) + (uint32_t)(kr * WS_STR + n4) * 4;
    }

#define P1_ISSUE(s, k0) { \
    _Pragma("unroll") for (int j = 0; j < 4; j++) \
        CP16(xdst[j] + (s) * 18432, xgp[j] + (k0)); \
    _Pragma("unroll") for (int j = 0; j < 2; j++) \
        CP16(wdst[j] + (s) * 9216, wgp[j] + (size_t)(k0) * R); \
    CP_COMMIT(); }

    float acc[8][4];
#pragma unroll
    for (int i = 0; i < 8; i++)
#pragma unroll
        for (int j = 0; j < 4; j++) acc[i][j] = 0.f;

    P1_ISSUE(0, 0);
    P1_ISSUE(1, 32);

    for (int it = 0; it < 24; it++) {
        const int p = it & 1;
        if (it < 23) { CP_WAIT1(); } else { CP_WAIT0(); }
        __syncthreads();
        const float* XA = SM + (size_t)p * 4608 + m0 * XS_STR;
        const float* WB = SM + (WS_B(p) >> 2);
#pragma unroll
        for (int ks = 0; ks < 4; ks++) {
            const int kk = ks * 8;
            const float* xb = XA + kk;
            uint32_t a0 = FB(tf32f(xb[(size_t)lr * XS_STR + lc]));
            uint32_t a1 = FB(tf32f(xb[(size_t)(lr + 8) * XS_STR + lc]));
            uint32_t a2 = FB(tf32f(xb[(size_t)lr * XS_STR + lc + 4]));
            uint32_t a3 = FB(tf32f(xb[(size_t)(lr + 8) * XS_STR + lc + 4]));
            const float* wb0 = WB + (size_t)(kk + lc) * WS_STR + lr;
            const float* wb1 = WB + (size_t)(kk + lc + 4) * WS_STR + lr;
#pragma unroll
            for (int nt = 0; nt < 8; nt++) {
                uint32_t b0 = FB(wb0[nt * 8]);
                uint32_t b1v = FB(wb1[nt * 8]);
                mma_tf32(acc[nt], a0, a1, a2, a3, b0, b1v);
            }
        }
        if (it < 22) {
            __syncthreads();
            P1_ISSUE(p, (it + 2) * 32);
        }
    }
    __syncthreads();   // all phase-1 reads done before pool reuse

    // bias + gelu -> HS (tf32-rounded); rows are warp-private
#pragma unroll
    for (int nt = 0; nt < 8; nt++) {
        const int cb = nt * 8 + 2 * lc;
        const float bva = b1s[cb], bvb = b1s[cb + 1];
        float* h0 = HSf + (size_t)(m0 + lr) * HS_STR + cb;
        float* h1 = HSf + (size_t)(m0 + lr + 8) * HS_STR + cb;
        h0[0] = tf32f(gelu(acc[nt][0] + bva));
        h0[1] = tf32f(gelu(acc[nt][1] + bvb));
        h1[0] = tf32f(gelu(acc[nt][2] + bva));
        h1[1] = tf32f(gelu(acc[nt][3] + bvb));
    }
    __syncwarp();

    // preload phase-2 A fragments (K=64) from own warp's HS rows
    uint32_t af[8][4];
#pragma unroll
    for (int ks = 0; ks < 8; ks++) {
        const int kk = ks * 8;
        const float* hb = HSf + (size_t)m0 * HS_STR + kk;
        af[ks][0] = FB(hb[(size_t)lr * HS_STR + lc]);
        af[ks][1] = FB(hb[(size_t)(lr + 8) * HS_STR + lc]);
        af[ks][2] = FB(hb[(size_t)lr * HS_STR + lc + 4]);
        af[ks][3] = FB(hb[(size_t)(lr + 8) * HS_STR + lc + 4]);
    }

    // ======== Phase 2: out[128,768] = gelu_h[128,64] @ W2[64,768] ========
    const float* w2e = g_w2r + (size_t)e * R * H;
    const float* w2gp[4]; uint32_t w2dst[4];
#pragma unroll
    for (int j = 0; j < 4; j++) {
        int i = tid + j * 256;
        int kr = i >> 4, n4 = (i & 15) << 2;
        w2gp[j]  = w2e + (size_t)kr * H + n4;
        w2dst[j] = sb + (uint32_t)(kr * WS_STR + n4) * 4;
    }
#define P2_ISSUE(b, n0) { \
    _Pragma("unroll") for (int j = 0; j < 4; j++) \
        CP16(w2dst[j] + (b) * 18432, w2gp[j] + (n0)); \
    CP_COMMIT(); }

    const bool ok0 = (m0 + lr) < nt_lim;
    const bool ok1 = (m0 + lr + 8) < nt_lim;
    const float pm0 = pm_s[m0 + lr];
    const float pm1 = pm_s[m0 + lr + 8];
    float* orow0 = outp + (size_t)toks[m0 + lr] * H;
    float* orow1 = outp + (size_t)toks[m0 + lr + 8] * H;

    P2_ISSUE(0, 0);
    if (tid < 64) b2s[tid] = b2[(size_t)e * H + tid];

    for (int nc = 0; nc < 12; nc++) {
        const int bf = nc & 1;
        const int n0 = nc * 64;
        CP_WAIT0();
        __syncthreads();
        if (nc < 11) {
            P2_ISSUE(bf ^ 1, n0 + 64);
            if (tid < 64) b2s[(bf ^ 1) * 64 + tid] = b2[(size_t)e * H + n0 + 64 + tid];
        }

        float acc2[8][4];
#pragma unroll
        for (int i = 0; i < 8; i++)
#pragma unroll
            for (int j = 0; j < 4; j++) acc2[i][j] = 0.f;

        const float* W2B = SM + (size_t)bf * 4608;
#pragma unroll
        for (int ks = 0; ks < 8; ks++) {
            const int kk = ks * 8;
            const float* wb0 = W2B + (size_t)(kk + lc) * WS_STR + lr;
            const float* wb1 = W2B + (size_t)(kk + lc + 4) * WS_STR + lr;
#pragma unroll
            for (int nt = 0; nt < 8; nt++) {
                uint32_t b0 = FB(wb0[nt * 8]);
                uint32_t b1v = FB(wb1[nt * 8]);
                mma_tf32(acc2[nt], af[ks][0], af[ks][1], af[ks][2], af[ks][3], b0, b1v);
            }
        }

#pragma unroll
        for (int nt = 0; nt < 8; nt++) {
            const int cb = nt * 8 + 2 * lc;
            const float bva = b2s[bf * 64 + cb], bvb = b2s[bf * 64 + cb + 1];
            if (ok0) {
                float2 o = { (acc2[nt][0] + bva) * pm0, (acc2[nt][1] + bvb) * pm0 };
                *(float2*)(orow0 + n0 + cb) = o;
            }
            if (ok1) {
                float2 o = { (acc2[nt][2] + bva) * pm1, (acc2[nt][3] + bvb) * pm1 };
                *(float2*)(orow1 + n0 + cb) = o;
            }
        }
    }
}

// ---------------- launch ----------------------------------------------------
extern "C" void kernel_launch(void* const* d_in, const int* in_sizes, int n_in,
                              void* d_out, int out_size) {
    const float* x     = (const float*)d_in[0];
    const float* enc_w = (const float*)d_in[1];
    const float* enc_b = (const float*)d_in[2];
    const float* sw_w  = (const float*)d_in[3];
    const float* sw_b  = (const float*)d_in[4];
    const float* w1    = (const float*)d_in[5];
    const float* b1    = (const float*)d_in[6];
    const float* w2    = (const float*)d_in[7];
    const float* b2    = (const float*)d_in[8];
    float* out = (float*)d_out;

    cudaFuncSetAttribute(expert_mma_kernel,
                         cudaFuncAttributeMaxDynamicSharedMemorySize, SMEM_TOTAL);

    router_prep_kernel<<<120, 256>>>(enc_w, enc_b, sw_w, sw_b, w1, w2);
    router_lite_kernel<<<T_TOT / 32, 256>>>(x);
    expert_mma_kernel<<<EXPERT_BLOCKS, 256, SMEM_TOTAL>>>(x, b1, b2, out);
}